// round 3
// baseline (speedup 1.0000x reference)
#include <cuda_runtime.h>
#include <math.h>

// Problem constants (fixed by the reference setup)
#define SS        7          // output bins per dim
#define NPROP     32
#define NCH       128
#define FD        32         // D/SCALE
#define FH        64         // H/SCALE
#define FW        64         // W/SCALE
#define LMAX      18         // max crop extent per dim: 64/4 + 2
#define THREADS   256

__global__ __launch_bounds__(THREADS)
void crop_roi_kernel(const float* __restrict__ f,
                     const float* __restrict__ proposals,
                     float* __restrict__ out)
{
    __shared__ float crop[LMAX * LMAX * LMAX];   // 23328 B

    const int n   = blockIdx.x;
    const int c   = blockIdx.y;
    const int tid = threadIdx.x;

    // Every thread redundantly computes the crop box (cheap, broadcast loads).
    const float* p = proposals + n * 8;
    const int b = (int)p[0];

    int c0[3], L[3];
    const int dims[3] = {FD, FH, FW};
#pragma unroll
    for (int d = 0; d < 3; d++) {
        const float ctr = p[2 + d];
        const float sd  = p[5 + d];
        int lo = (int)floorf((ctr - 0.5f * sd) * 0.25f);
        int hi = (int)ceilf ((ctr + 0.5f * sd) * 0.25f);
        lo = max(lo, 0);
        hi = min(hi, dims[d]);
        c0[d] = lo;
        L[d]  = hi - lo;      // guaranteed >= 1 (side >= 16)
    }

    const int Lz = L[0], Ly = L[1], Lx = L[2];
    const int tot = Lz * Ly * Lx;

    // Stage the crop into smem, coalesced along x.
    const float* fb = f + ((size_t)b * NCH + c) * (size_t)(FD * FH * FW);
    const int base = (c0[0] * FH + c0[1]) * FW + c0[2];
    for (int i = tid; i < tot; i += THREADS) {
        const int x = i % Lx;
        const int t = i / Lx;
        const int y = t % Ly;
        const int z = t / Ly;
        crop[i] = __ldg(&fb[base + (z * FH + y) * FW + x]);
    }
    __syncthreads();

    // Each thread computes one or two of the 343 output bins.
    float* outp = out + ((size_t)n * NCH + c) * (SS * SS * SS);
    for (int bin = tid; bin < SS * SS * SS; bin += THREADS) {
        const int bx = bin % SS;
        const int t1 = bin / SS;
        const int by = t1 % SS;
        const int bz = t1 / SS;

        const int z0 =  bz      * Lz / SS;
        const int z1 = ((bz + 1) * Lz + SS - 1) / SS;
        const int y0 =  by      * Ly / SS;
        const int y1 = ((by + 1) * Ly + SS - 1) / SS;
        const int x0 =  bx      * Lx / SS;
        const int x1 = ((bx + 1) * Lx + SS - 1) / SS;

        float m = -INFINITY;
        for (int z = z0; z < z1; z++) {
            const int zb = z * Ly;
            for (int y = y0; y < y1; y++) {
                const int yb = (zb + y) * Lx;
                for (int x = x0; x < x1; x++) {
                    m = fmaxf(m, crop[yb + x]);
                }
            }
        }
        outp[bin] = m;
    }
}

extern "C" void kernel_launch(void* const* d_in, const int* in_sizes, int n_in,
                              void* d_out, int out_size)
{
    const float* f         = (const float*)d_in[0];
    // d_in[1] = inputs, only used for shape in the reference (static here)
    const float* proposals = (const float*)d_in[2];
    float* out = (float*)d_out;

    dim3 grid(NPROP, NCH);
    crop_roi_kernel<<<grid, THREADS>>>(f, proposals, out);
}